// round 1
// baseline (speedup 1.0000x reference)
#include <cuda_runtime.h>
#include <math.h>

#define SEQ 2048
#define DIM 3072
#define NH 24
#define HD 128
#define RANK 16
#define QKV_N (3 * DIM)
#define LORA_SCALE 1.0f

// ---------------- scratch (device globals; no allocations allowed) ----------
__device__ float g_qkv[(size_t)SEQ * QKV_N];       // [L, 9216]
__device__ float g_xa[SEQ * RANK];                 // x @ qkv_down^T
__device__ float g_q[(size_t)NH * SEQ * HD];
__device__ float g_k[(size_t)NH * SEQ * HD];
__device__ float g_v[(size_t)NH * SEQ * HD];
__device__ float g_o[(size_t)SEQ * DIM];           // attention output, [L, 3072]
__device__ float g_ob[SEQ * RANK];                 // o @ proj_down^T

// ---------------- LoRA down-projection: out[M,16] = A[M,K] @ D[16,K]^T ------
__global__ void __launch_bounds__(256) lora_down_k(
    const float* __restrict__ A, const float* __restrict__ D,
    float* __restrict__ out)
{
    int m = blockIdx.x * 16 + (threadIdx.x >> 4);
    int r = threadIdx.x & 15;
    const float4* a4 = (const float4*)(A + (size_t)m * DIM);
    const float4* d4 = (const float4*)(D + (size_t)r * DIM);
    float acc = 0.f;
#pragma unroll 4
    for (int k = 0; k < DIM / 4; k++) {
        float4 va = a4[k], vd = d4[k];
        acc = fmaf(va.x, vd.x, acc);
        acc = fmaf(va.y, vd.y, acc);
        acc = fmaf(va.z, vd.z, acc);
        acc = fmaf(va.w, vd.w, acc);
    }
    out[m * RANK + r] = acc;
}

// ---------------- SGEMM (NT) with bias + rank-16 LoRA epilogue --------------
// C[m,n] = sum_k A[m,k]*W[n,k] + bias[n] + LORA_SCALE * sum_r LA[m,r]*LU[n,r]
__global__ void __launch_bounds__(256) sgemm_lora_k(
    const float* __restrict__ A, const float* __restrict__ W,
    const float* __restrict__ bias,
    const float* __restrict__ LA, const float* __restrict__ LU,
    float* __restrict__ C, int N, int K)
{
    __shared__ float As[16][128];
    __shared__ float Bs[16][128];
    __shared__ float LAs[128][16];
    __shared__ float LUs[128][16];

    const int tid = threadIdx.x;
    const int bm = blockIdx.y * 128;
    const int bn = blockIdx.x * 128;

    {   // LoRA operand tiles: 2x (128x16) = 2x2048 floats, 2 float4 per thread
        int idx = tid * 2;
#pragma unroll
        for (int i = 0; i < 2; i++, idx++) {
            int r = idx >> 2, c = (idx & 3) * 4;
            *(float4*)&LAs[r][c] = *(const float4*)&LA[(size_t)(bm + r) * RANK + c];
            *(float4*)&LUs[r][c] = *(const float4*)&LU[(size_t)(bn + r) * RANK + c];
        }
    }

    const int lr = tid >> 2;           // 0..63 (+64 on 2nd pass)
    const int lc = (tid & 3) * 4;      // 0,4,8,12
    const int trow = (tid >> 4) * 8;
    const int tcol = (tid & 15) * 8;

    float acc[8][8] = {};

    for (int k0 = 0; k0 < K; k0 += 16) {
#pragma unroll
        for (int i = 0; i < 2; i++) {
            int r = lr + i * 64;
            float4 va = *(const float4*)&A[(size_t)(bm + r) * K + k0 + lc];
            As[lc + 0][r] = va.x; As[lc + 1][r] = va.y;
            As[lc + 2][r] = va.z; As[lc + 3][r] = va.w;
            float4 vb = *(const float4*)&W[(size_t)(bn + r) * K + k0 + lc];
            Bs[lc + 0][r] = vb.x; Bs[lc + 1][r] = vb.y;
            Bs[lc + 2][r] = vb.z; Bs[lc + 3][r] = vb.w;
        }
        __syncthreads();
#pragma unroll
        for (int k = 0; k < 16; k++) {
            float ra[8], rb[8];
            *(float4*)&ra[0] = *(const float4*)&As[k][trow];
            *(float4*)&ra[4] = *(const float4*)&As[k][trow + 4];
            *(float4*)&rb[0] = *(const float4*)&Bs[k][tcol];
            *(float4*)&rb[4] = *(const float4*)&Bs[k][tcol + 4];
#pragma unroll
            for (int i = 0; i < 8; i++)
#pragma unroll
                for (int j = 0; j < 8; j++)
                    acc[i][j] = fmaf(ra[i], rb[j], acc[i][j]);
        }
        __syncthreads();
    }

#pragma unroll
    for (int i = 0; i < 8; i++) {
        size_t mrow = (size_t)(bm + trow + i) * N;
#pragma unroll
        for (int j = 0; j < 8; j++) {
            int n = bn + tcol + j;
            float l = 0.f;
#pragma unroll
            for (int r2 = 0; r2 < RANK; r2++)
                l = fmaf(LAs[trow + i][r2], LUs[tcol + j][r2], l);
            C[mrow + n] = acc[i][j] + bias[n] + LORA_SCALE * l;
        }
    }
}

// ---------------- per-(l,h): QK RMSNorm + RoPE, repack q/k/v head-major -----
__global__ void __launch_bounds__(128) norm_rope_k(
    const float* __restrict__ pe,
    const float* __restrict__ q_scale, const float* __restrict__ k_scale)
{
    int l = blockIdx.x, h = blockIdx.y;
    int t = threadIdx.x;                        // 0..127
    const float* row = g_qkv + (size_t)l * QKV_N + h * HD;
    float qv = row[t];
    float kv = row[DIM + t];
    float vv = row[2 * DIM + t];

    __shared__ float red[8];
    __shared__ float qrow[HD], krow[HD];
    float s1 = qv * qv, s2 = kv * kv;
#pragma unroll
    for (int o = 16; o > 0; o >>= 1) {
        s1 += __shfl_xor_sync(0xffffffffu, s1, o);
        s2 += __shfl_xor_sync(0xffffffffu, s2, o);
    }
    if ((t & 31) == 0) { red[t >> 5] = s1; red[4 + (t >> 5)] = s2; }
    __syncthreads();
    float msq = (red[0] + red[1] + red[2] + red[3]) * (1.f / HD);
    float msk = (red[4] + red[5] + red[6] + red[7]) * (1.f / HD);
    qrow[t] = qv * rsqrtf(msq + 1e-6f) * q_scale[t];
    krow[t] = kv * rsqrtf(msk + 1e-6f) * k_scale[t];
    __syncthreads();

    int i = t >> 1;
    const float* p = pe + ((size_t)l * (HD / 2) + i) * 4;   // [cos,-sin,sin,cos]
    float c = p[0], s = p[2];
    float q0 = qrow[2 * i], q1 = qrow[2 * i + 1];
    float k0 = krow[2 * i], k1 = krow[2 * i + 1];
    float qo = (t & 1) ? fmaf(s, q0, c * q1) : fmaf(c, q0, -s * q1);
    float ko = (t & 1) ? fmaf(s, k0, c * k1) : fmaf(c, k0, -s * k1);

    size_t oidx = ((size_t)h * SEQ + l) * HD + t;
    g_q[oidx] = qo;
    g_k[oidx] = ko;
    g_v[oidx] = vv;
}

// ---------------- flash attention, fp32, 64x64 tiles ------------------------
#define FA_BM 64
#define FA_BN 64
#define QPAD 129
#define SPAD 65
#define FA_SMEM ((3 * FA_BM * QPAD + FA_BM * SPAD + FA_BM) * sizeof(float))

__global__ void __launch_bounds__(256) flash_k()
{
    extern __shared__ float sm[];
    float* Qs = sm;                         // 64 x 129
    float* Ks = Qs + FA_BM * QPAD;          // 64 x 129
    float* Vs = Ks + FA_BM * QPAD;          // 64 x 129
    float* Ss = Vs + FA_BM * QPAD;          // 64 x 65
    float* Ls = Ss + FA_BM * SPAD;          // 64

    const int h = blockIdx.y;
    const int q0 = blockIdx.x * FA_BM;
    const int tid = threadIdx.x;

    const float* Qg = g_q + ((size_t)h * SEQ + q0) * HD;
    const float* Kg = g_k + (size_t)h * SEQ * HD;
    const float* Vg = g_v + (size_t)h * SEQ * HD;

    for (int i = tid; i < FA_BM * HD / 4; i += 256) {
        int r = i >> 5, c = (i & 31) * 4;
        float4 v4 = *(const float4*)&Qg[(size_t)r * HD + c];
        Qs[r * QPAD + c + 0] = v4.x; Qs[r * QPAD + c + 1] = v4.y;
        Qs[r * QPAD + c + 2] = v4.z; Qs[r * QPAD + c + 3] = v4.w;
    }

    const int srow = (tid >> 4) * 4;    // S-compute mapping: 16x16 thr, 4x4 tile
    const int scol = (tid & 15) * 4;
    const int row = tid & 63;           // softmax/PV mapping
    const int cb = (tid >> 6) * 32;

    float o[32];
#pragma unroll
    for (int c = 0; c < 32; c++) o[c] = 0.f;
    float mi = -1e30f, li = 0.f;
    const float scale = 0.088388347648318447f;  // 1/sqrt(128)

    __syncthreads();

    for (int kt = 0; kt < SEQ; kt += FA_BN) {
        for (int i = tid; i < FA_BN * HD / 4; i += 256) {
            int r = i >> 5, c = (i & 31) * 4;
            float4 k4 = *(const float4*)&Kg[(size_t)(kt + r) * HD + c];
            Ks[r * QPAD + c + 0] = k4.x; Ks[r * QPAD + c + 1] = k4.y;
            Ks[r * QPAD + c + 2] = k4.z; Ks[r * QPAD + c + 3] = k4.w;
            float4 v4 = *(const float4*)&Vg[(size_t)(kt + r) * HD + c];
            Vs[r * QPAD + c + 0] = v4.x; Vs[r * QPAD + c + 1] = v4.y;
            Vs[r * QPAD + c + 2] = v4.z; Vs[r * QPAD + c + 3] = v4.w;
        }
        __syncthreads();

        // S = Q K^T * scale
        float sacc[4][4] = {};
        for (int k = 0; k < HD; k++) {
            float qa[4], kb[4];
#pragma unroll
            for (int i2 = 0; i2 < 4; i2++) qa[i2] = Qs[(srow + i2) * QPAD + k];
#pragma unroll
            for (int j = 0; j < 4; j++) kb[j] = Ks[(scol + j) * QPAD + k];
#pragma unroll
            for (int i2 = 0; i2 < 4; i2++)
#pragma unroll
                for (int j = 0; j < 4; j++)
                    sacc[i2][j] = fmaf(qa[i2], kb[j], sacc[i2][j]);
        }
#pragma unroll
        for (int i2 = 0; i2 < 4; i2++)
#pragma unroll
            for (int j = 0; j < 4; j++)
                Ss[(srow + i2) * SPAD + scol + j] = sacc[i2][j] * scale;
        __syncthreads();

        // online softmax: row stats replicated across the 4 threads of a row
        float rmax = -1e30f;
#pragma unroll 8
        for (int j = 0; j < FA_BN; j++) rmax = fmaxf(rmax, Ss[row * SPAD + j]);
        float mnew = fmaxf(mi, rmax);
        float corr = __expf(mi - mnew);
        __syncthreads();                 // all rmax reads done before P overwrite
        if (tid < 64) {
            float lsum = 0.f;
#pragma unroll 8
            for (int j = 0; j < FA_BN; j++) {
                float p = __expf(Ss[row * SPAD + j] - mnew);
                Ss[row * SPAD + j] = p;
                lsum += p;
            }
            Ls[row] = lsum;
        }
#pragma unroll
        for (int c = 0; c < 32; c++) o[c] *= corr;
        __syncthreads();
        li = li * corr + Ls[row];
        mi = mnew;

        // O += P @ V (V row reads broadcast across warp)
        for (int j = 0; j < FA_BN; j++) {
            float p = Ss[row * SPAD + j];
            const float* vrow = &Vs[j * QPAD + cb];
#pragma unroll
            for (int c = 0; c < 32; c++) o[c] = fmaf(p, vrow[c], o[c]);
        }
        __syncthreads();
    }

    float inv = 1.f / li;
    float* orow = g_o + (size_t)(q0 + row) * DIM + h * HD + cb;
#pragma unroll
    for (int c = 0; c < 32; c++) orow[c] = o[c] * inv;
}

// ---------------- launch -----------------------------------------------------
extern "C" void kernel_launch(void* const* d_in, const int* in_sizes, int n_in,
                              void* d_out, int out_size)
{
    const float* x         = (const float*)d_in[0];
    const float* pe        = (const float*)d_in[1];
    const float* qkv_w     = (const float*)d_in[2];
    const float* qkv_b     = (const float*)d_in[3];
    const float* proj_w    = (const float*)d_in[4];
    const float* proj_b    = (const float*)d_in[5];
    const float* qkv_down  = (const float*)d_in[6];
    const float* qkv_up    = (const float*)d_in[7];
    const float* proj_down = (const float*)d_in[8];
    const float* proj_up   = (const float*)d_in[9];
    const float* q_scale   = (const float*)d_in[10];
    const float* k_scale   = (const float*)d_in[11];
    float* out = (float*)d_out;
    (void)in_sizes; (void)n_in; (void)out_size; (void)q_scale; (void)k_scale;

    float *gqkv, *gxa, *go, *gob;
    cudaGetSymbolAddress((void**)&gqkv, g_qkv);
    cudaGetSymbolAddress((void**)&gxa,  g_xa);
    cudaGetSymbolAddress((void**)&go,   g_o);
    cudaGetSymbolAddress((void**)&gob,  g_ob);

    cudaFuncSetAttribute(flash_k, cudaFuncAttributeMaxDynamicSharedMemorySize,
                         (int)FA_SMEM);

    // 1) xa = x @ qkv_down^T
    lora_down_k<<<SEQ / 16, 256>>>(x, qkv_down, gxa);
    // 2) qkv = x @ qkv_w^T + b + xa @ qkv_up^T
    sgemm_lora_k<<<dim3(QKV_N / 128, SEQ / 128), 256>>>(
        x, qkv_w, qkv_b, gxa, qkv_up, gqkv, QKV_N, DIM);
    // 3) RMSNorm(q,k) + RoPE, repack head-major
    norm_rope_k<<<dim3(SEQ, NH), 128>>>(pe, q_scale, k_scale);
    // 4) flash attention -> g_o [L, 3072]
    flash_k<<<dim3(SEQ / FA_BM, NH), 256, FA_SMEM>>>();
    // 5) ob = o @ proj_down^T
    lora_down_k<<<SEQ / 16, 256>>>(go, proj_down, gob);
    // 6) out = o @ proj_w^T + b + ob @ proj_up^T
    sgemm_lora_k<<<dim3(DIM / 128, SEQ / 128), 256>>>(
        go, proj_w, proj_b, gob, proj_up, out, DIM, DIM);
}

// round 3
// speedup vs baseline: 3.0589x; 3.0589x over previous
#include <cuda_runtime.h>
#include <cuda_bf16.h>
#include <math.h>

#define SEQ 2048
#define DIM 3072
#define NH 24
#define HD 128
#define RANK 16
#define QKV_N (3 * DIM)
#define LORA_SCALE 1.0f
#define SEQW (SEQ / 2)

// ---------------- scratch (device globals; no allocations allowed) ----------
__device__ float g_qkv[(size_t)SEQ * QKV_N];
__device__ float g_xa[SEQ * RANK];
__device__ float g_ob[SEQ * RANK];
__device__ float g_o[(size_t)SEQ * DIM];

// packed bf16-pair (hi/lo split) word arrays
__device__ unsigned g_x2h[(size_t)SEQ * DIM / 2],   g_x2l[(size_t)SEQ * DIM / 2];
__device__ unsigned g_w1h[(size_t)QKV_N * DIM / 2], g_w1l[(size_t)QKV_N * DIM / 2];
__device__ unsigned g_w2h[(size_t)DIM * DIM / 2],   g_w2l[(size_t)DIM * DIM / 2];
__device__ unsigned g_o2h[(size_t)SEQ * DIM / 2],   g_o2l[(size_t)SEQ * DIM / 2];
__device__ unsigned g_u1h[QKV_N * RANK / 2],        g_u1l[QKV_N * RANK / 2];
__device__ unsigned g_u2h[DIM * RANK / 2],          g_u2l[DIM * RANK / 2];
__device__ unsigned g_xa2h[SEQ * RANK / 2],         g_xa2l[SEQ * RANK / 2];
__device__ unsigned g_ob2h[SEQ * RANK / 2],         g_ob2l[SEQ * RANK / 2];
__device__ unsigned g_q2h[(size_t)NH * SEQ * HD / 2], g_q2l[(size_t)NH * SEQ * HD / 2];
__device__ unsigned g_k2h[(size_t)NH * SEQ * HD / 2], g_k2l[(size_t)NH * SEQ * HD / 2];
__device__ unsigned g_v2h[(size_t)NH * HD * SEQW],    g_v2l[(size_t)NH * HD * SEQW];

// ---------------- helpers ----------------------------------------------------
__device__ __forceinline__ void mma_bf16(float* d, const unsigned* a, const unsigned* b)
{
    asm volatile(
        "mma.sync.aligned.m16n8k16.row.col.f32.bf16.bf16.f32 "
        "{%0,%1,%2,%3},{%4,%5,%6,%7},{%8,%9},{%0,%1,%2,%3};\n"
        : "+f"(d[0]), "+f"(d[1]), "+f"(d[2]), "+f"(d[3])
        : "r"(a[0]), "r"(a[1]), "r"(a[2]), "r"(a[3]), "r"(b[0]), "r"(b[1]));
}

__device__ __forceinline__ unsigned packbf(float v0, float v1)
{   // v0 -> low half (element k), v1 -> high half (element k+1)
    unsigned r;
    asm("cvt.rn.bf16x2.f32 %0, %1, %2;" : "=r"(r) : "f"(v1), "f"(v0));
    return r;
}
__device__ __forceinline__ float2 unpackbf(unsigned w)
{
    float2 f;
    f.x = __uint_as_float(w << 16);
    f.y = __uint_as_float(w & 0xffff0000u);
    return f;
}

// fast e^(x*ln2-ish): 2^x via rint + degree-5 poly (rel err ~3e-6)
__device__ __forceinline__ float exp2t(float x)
{
    x = fmaxf(x, -120.f);
    float r = rintf(x);
    float t = (x - r) * 0.6931471805599453f;
    float p = fmaf(t, 0.0083333333f, 0.041666666f);
    p = fmaf(t, p, 0.16666667f);
    p = fmaf(t, p, 0.5f);
    p = fmaf(t, p, 1.0f);
    p = fmaf(t, p, 1.0f);
    return __int_as_float(__float_as_int(p) + (((int)r) << 23));
}

// ---------------- fp32 -> (hi, lo) bf16-pair pack -----------------------------
__global__ void __launch_bounds__(256) convert_pack_k(
    const float4* __restrict__ in, uint2* __restrict__ hi, uint2* __restrict__ lo, int n4)
{
    int i = blockIdx.x * 256 + threadIdx.x;
    if (i >= n4) return;
    float4 v = in[i];
    unsigned h0 = packbf(v.x, v.y), h1 = packbf(v.z, v.w);
    float2 a = unpackbf(h0), b = unpackbf(h1);
    unsigned l0 = packbf(v.x - a.x, v.y - a.y);
    unsigned l1 = packbf(v.z - b.x, v.w - b.y);
    hi[i] = make_uint2(h0, h1);
    lo[i] = make_uint2(l0, l1);
}

// ---------------- LoRA down-projection: out[M,16] = A[M,K] @ D[16,K]^T --------
__global__ void __launch_bounds__(256) lora_down_k(
    const float* __restrict__ A, const float* __restrict__ D, float* __restrict__ out)
{
    int m = blockIdx.x * 16 + (threadIdx.x >> 4);
    int r = threadIdx.x & 15;
    const float4* a4 = (const float4*)(A + (size_t)m * DIM);
    const float4* d4 = (const float4*)(D + (size_t)r * DIM);
    float acc = 0.f;
#pragma unroll 4
    for (int k = 0; k < DIM / 4; k++) {
        float4 va = a4[k], vd = d4[k];
        acc = fmaf(va.x, vd.x, acc);
        acc = fmaf(va.y, vd.y, acc);
        acc = fmaf(va.z, vd.z, acc);
        acc = fmaf(va.w, vd.w, acc);
    }
    out[m * RANK + r] = acc * LORA_SCALE;
}

// ---------------- split-bf16 GEMM (NT) + bias + LoRA extra K-step -------------
// C[m,n] = sum_k A[m,k]W[n,k] + bias[n] + sum_r LA[m,r]LU[n,r]
__global__ void __launch_bounds__(256) gemm_bf16s_lora_k(
    const unsigned* __restrict__ Ahg, const unsigned* __restrict__ Alg,
    const unsigned* __restrict__ Whg, const unsigned* __restrict__ Wlg,
    const float* __restrict__ bias,
    const unsigned* __restrict__ LAh, const unsigned* __restrict__ LAl,
    const unsigned* __restrict__ LUh, const unsigned* __restrict__ LUl,
    float* __restrict__ C, int N, int K)
{
    const int Kw = K / 2;
    __shared__ unsigned Ah[128][20], Al[128][20], Bh[128][20], Bl[128][20];

    const int tid = threadIdx.x;
    const int lane = tid & 31, wid = tid >> 5;
    const int wm = (wid & 1) * 64, wn = (wid >> 1) * 32;
    const int gr = lane >> 2, gc = lane & 3;
    const int bm = blockIdx.y * 128, bn = blockIdx.x * 128;

    float acc[4][4][4];
#pragma unroll
    for (int i = 0; i < 4; i++)
#pragma unroll
        for (int j = 0; j < 4; j++)
#pragma unroll
            for (int q = 0; q < 4; q++) acc[i][j][q] = 0.f;

    for (int k0 = 0; k0 < Kw; k0 += 16) {
#pragma unroll
        for (int i = 0; i < 2; i++) {
            int row = (tid >> 2) + i * 64, wq = (tid & 3) * 4;
            size_t ai = (size_t)(bm + row) * Kw + k0 + wq;
            size_t bi = (size_t)(bn + row) * Kw + k0 + wq;
            *(uint4*)&Ah[row][wq] = *(const uint4*)&Ahg[ai];
            *(uint4*)&Al[row][wq] = *(const uint4*)&Alg[ai];
            *(uint4*)&Bh[row][wq] = *(const uint4*)&Whg[bi];
            *(uint4*)&Bl[row][wq] = *(const uint4*)&Wlg[bi];
        }
        __syncthreads();
#pragma unroll
        for (int kk = 0; kk < 2; kk++) {
            unsigned ah[4][4], al[4][4], bh[4][2], bl[4][2];
#pragma unroll
            for (int mi = 0; mi < 4; mi++) {
                int rb = wm + mi * 16 + gr, c0 = kk * 8 + gc;
                ah[mi][0] = Ah[rb][c0];     ah[mi][1] = Ah[rb + 8][c0];
                ah[mi][2] = Ah[rb][c0 + 4]; ah[mi][3] = Ah[rb + 8][c0 + 4];
                al[mi][0] = Al[rb][c0];     al[mi][1] = Al[rb + 8][c0];
                al[mi][2] = Al[rb][c0 + 4]; al[mi][3] = Al[rb + 8][c0 + 4];
            }
#pragma unroll
            for (int ni = 0; ni < 4; ni++) {
                int nb = wn + ni * 8 + gr, c0 = kk * 8 + gc;
                bh[ni][0] = Bh[nb][c0]; bh[ni][1] = Bh[nb][c0 + 4];
                bl[ni][0] = Bl[nb][c0]; bl[ni][1] = Bl[nb][c0 + 4];
            }
#pragma unroll
            for (int mi = 0; mi < 4; mi++)
#pragma unroll
                for (int ni = 0; ni < 4; ni++) {
                    mma_bf16(acc[mi][ni], ah[mi], bh[ni]);
                    mma_bf16(acc[mi][ni], ah[mi], bl[ni]);
                    mma_bf16(acc[mi][ni], al[mi], bh[ni]);
                }
        }
        __syncthreads();
    }

    // LoRA: one extra k16 step (rank 16 = 8 words)
    {
        int row = tid >> 1, wq = (tid & 1) * 4;
        *(uint4*)&Ah[row][wq] = *(const uint4*)&LAh[(size_t)(bm + row) * 8 + wq];
        *(uint4*)&Al[row][wq] = *(const uint4*)&LAl[(size_t)(bm + row) * 8 + wq];
        *(uint4*)&Bh[row][wq] = *(const uint4*)&LUh[(size_t)(bn + row) * 8 + wq];
        *(uint4*)&Bl[row][wq] = *(const uint4*)&LUl[(size_t)(bn + row) * 8 + wq];
        __syncthreads();
        unsigned ah[4][4], al[4][4], bh[4][2], bl[4][2];
#pragma unroll
        for (int mi = 0; mi < 4; mi++) {
            int rb = wm + mi * 16 + gr;
            ah[mi][0] = Ah[rb][gc];     ah[mi][1] = Ah[rb + 8][gc];
            ah[mi][2] = Ah[rb][gc + 4]; ah[mi][3] = Ah[rb + 8][gc + 4];
            al[mi][0] = Al[rb][gc];     al[mi][1] = Al[rb + 8][gc];
            al[mi][2] = Al[rb][gc + 4]; al[mi][3] = Al[rb + 8][gc + 4];
        }
#pragma unroll
        for (int ni = 0; ni < 4; ni++) {
            int nb = wn + ni * 8 + gr;
            bh[ni][0] = Bh[nb][gc]; bh[ni][1] = Bh[nb][gc + 4];
            bl[ni][0] = Bl[nb][gc]; bl[ni][1] = Bl[nb][gc + 4];
        }
#pragma unroll
        for (int mi = 0; mi < 4; mi++)
#pragma unroll
            for (int ni = 0; ni < 4; ni++) {
                mma_bf16(acc[mi][ni], ah[mi], bh[ni]);
                mma_bf16(acc[mi][ni], ah[mi], bl[ni]);
                mma_bf16(acc[mi][ni], al[mi], bh[ni]);
            }
    }

#pragma unroll
    for (int mi = 0; mi < 4; mi++) {
        int row = bm + wm + mi * 16 + gr;
#pragma unroll
        for (int ni = 0; ni < 4; ni++) {
            int col = bn + wn + ni * 8 + gc * 2;
            float b0 = __ldg(&bias[col]), b1 = __ldg(&bias[col + 1]);
            float2 v0 = {acc[mi][ni][0] + b0, acc[mi][ni][1] + b1};
            float2 v1 = {acc[mi][ni][2] + b0, acc[mi][ni][3] + b1};
            *(float2*)&C[(size_t)row * N + col] = v0;
            *(float2*)&C[(size_t)(row + 8) * N + col] = v1;
        }
    }
}

// ---------------- QK RMSNorm + RoPE; emit packed q/k (row) and v (transposed) -
// grid (SEQ/2, NH), 256 threads: half-block per token
__global__ void __launch_bounds__(256) norm_rope_k(
    const float* __restrict__ pe,
    const float* __restrict__ q_scale, const float* __restrict__ k_scale)
{
    const int half = threadIdx.x >> 7;
    const int t = threadIdx.x & 127;
    const int l = blockIdx.x * 2 + half;
    const int h = blockIdx.y;

    const float* row = g_qkv + (size_t)l * QKV_N + h * HD;
    float qv = row[t], kv = row[DIM + t], vv = row[2 * DIM + t];

    __shared__ float red[2][8];
    __shared__ float qr[2][HD], kr[2][HD], qo_[2][HD], ko_[2][HD], vr[2][HD];

    float s1 = qv * qv, s2 = kv * kv;
#pragma unroll
    for (int o = 16; o > 0; o >>= 1) {
        s1 += __shfl_xor_sync(0xffffffffu, s1, o);
        s2 += __shfl_xor_sync(0xffffffffu, s2, o);
    }
    int w = (t >> 5);
    if ((t & 31) == 0) { red[half][w] = s1; red[half][4 + w] = s2; }
    __syncthreads();
    float msq = (red[half][0] + red[half][1] + red[half][2] + red[half][3]) * (1.f / HD);
    float msk = (red[half][4] + red[half][5] + red[half][6] + red[half][7]) * (1.f / HD);
    qr[half][t] = qv * rsqrtf(msq + 1e-6f) * q_scale[t];
    kr[half][t] = kv * rsqrtf(msk + 1e-6f) * k_scale[t];
    vr[half][t] = vv;
    __syncthreads();

    int i = t >> 1;
    const float* p = pe + ((size_t)l * (HD / 2) + i) * 4;
    float c = p[0], s = p[2];
    float q0 = qr[half][2 * i], q1 = qr[half][2 * i + 1];
    float k0 = kr[half][2 * i], k1 = kr[half][2 * i + 1];
    qo_[half][t] = (t & 1) ? fmaf(s, q0, c * q1) : fmaf(c, q0, -s * q1);
    ko_[half][t] = (t & 1) ? fmaf(s, k0, c * k1) : fmaf(c, k0, -s * k1);
    __syncthreads();

    if (t < 64) {  // pack q/k words for this token
        size_t base = ((size_t)h * SEQ + l) * (HD / 2) + t;
        float a0 = qo_[half][2 * t], a1 = qo_[half][2 * t + 1];
        unsigned hq = packbf(a0, a1);
        float2 u = unpackbf(hq);
        g_q2h[base] = hq;
        g_q2l[base] = packbf(a0 - u.x, a1 - u.y);
        float b0 = ko_[half][2 * t], b1 = ko_[half][2 * t + 1];
        unsigned hk = packbf(b0, b1);
        u = unpackbf(hk);
        g_k2h[base] = hk;
        g_k2l[base] = packbf(b0 - u.x, b1 - u.y);
    }
    if (half == 0) {  // pack v transposed: word = (v[l0,d], v[l0+1,d])
        float v0 = vr[0][t], v1 = vr[1][t];
        unsigned hv = packbf(v0, v1);
        float2 u = unpackbf(hv);
        size_t base = ((size_t)h * HD + t) * SEQW + blockIdx.x;
        g_v2h[base] = hv;
        g_v2l[base] = packbf(v0 - u.x, v1 - u.y);
    }
}

// ---------------- flash attention, split-bf16 mma, 128x64 tiles ---------------
#define FBM 128
#define FBN 64
#define QSW 68    // Q/K smem row stride in words
#define VSW 36    // V^T smem row stride in words
#define FA_SMEM ((2 * FBM * QSW + 2 * FBN * QSW + 2 * FBM * VSW) * sizeof(unsigned))

__global__ void __launch_bounds__(256) flash_k()
{
    extern __shared__ unsigned smw[];
    unsigned* Qh = smw;
    unsigned* Ql = Qh + FBM * QSW;
    unsigned* Kh = Ql + FBM * QSW;
    unsigned* Kl = Kh + FBN * QSW;
    unsigned* Vh = Kl + FBN * QSW;
    unsigned* Vl = Vh + FBM * VSW;

    const int h = blockIdx.y;
    const int q0 = blockIdx.x * FBM;
    const int tid = threadIdx.x;
    const int lane = tid & 31, wid = tid >> 5;
    const int gr = lane >> 2, gc = lane & 3;
    const int rb = wid * 16;

    // Q tile: 128 rows x 64 words (x2 for hi/lo)
#pragma unroll
    for (int i = 0; i < 8; i++) {
        int idx = tid + i * 256;
        int r = idx >> 4, wq = (idx & 15) * 4;
        size_t src = ((size_t)h * SEQ + q0 + r) * 64 + wq;
        *(uint4*)&Qh[r * QSW + wq] = *(const uint4*)&g_q2h[src];
        *(uint4*)&Ql[r * QSW + wq] = *(const uint4*)&g_q2l[src];
    }

    float o[16][4];
#pragma unroll
    for (int i = 0; i < 16; i++)
#pragma unroll
        for (int j = 0; j < 4; j++) o[i][j] = 0.f;
    float m_lo = -1e30f, m_hi = -1e30f, l_lo = 0.f, l_hi = 0.f;
    const float SC2 = 0.088388347648318447f * 1.4426950408889634f;

    __syncthreads();

    for (int kt = 0; kt < SEQ; kt += FBN) {
#pragma unroll
        for (int i = 0; i < 4; i++) {
            int idx = tid + i * 256;
            int r = idx >> 4, wq = (idx & 15) * 4;
            size_t src = ((size_t)h * SEQ + kt + r) * 64 + wq;
            *(uint4*)&Kh[r * QSW + wq] = *(const uint4*)&g_k2h[src];
            *(uint4*)&Kl[r * QSW + wq] = *(const uint4*)&g_k2l[src];
            int rv = idx >> 3, wv = (idx & 7) * 4;
            size_t vsrc = ((size_t)h * HD + rv) * SEQW + kt / 2 + wv;
            *(uint4*)&Vh[rv * VSW + wv] = *(const uint4*)&g_v2h[vsrc];
            *(uint4*)&Vl[rv * VSW + wv] = *(const uint4*)&g_v2l[vsrc];
        }
        __syncthreads();

        // S = Q K^T
        float s[8][4];
#pragma unroll
        for (int i = 0; i < 8; i++)
#pragma unroll
            for (int j = 0; j < 4; j++) s[i][j] = 0.f;
#pragma unroll
        for (int kk = 0; kk < 8; kk++) {
            unsigned ah[4], al[4];
            int qb = (rb + gr) * QSW + kk * 8 + gc;
            ah[0] = Qh[qb]; ah[1] = Qh[qb + 8 * QSW];
            ah[2] = Qh[qb + 4]; ah[3] = Qh[qb + 8 * QSW + 4];
            al[0] = Ql[qb]; al[1] = Ql[qb + 8 * QSW];
            al[2] = Ql[qb + 4]; al[3] = Ql[qb + 8 * QSW + 4];
#pragma unroll
            for (int ni = 0; ni < 8; ni++) {
                int kb = (ni * 8 + gr) * QSW + kk * 8 + gc;
                unsigned bh[2] = {Kh[kb], Kh[kb + 4]};
                unsigned bl[2] = {Kl[kb], Kl[kb + 4]};
                mma_bf16(s[ni], ah, bh);
                mma_bf16(s[ni], ah, bl);
                mma_bf16(s[ni], al, bh);
            }
        }

        // online softmax (rows gr, gr+8)
        float rl = -1e30f, rh = -1e30f;
#pragma unroll
        for (int ni = 0; ni < 8; ni++) {
            rl = fmaxf(rl, fmaxf(s[ni][0], s[ni][1]));
            rh = fmaxf(rh, fmaxf(s[ni][2], s[ni][3]));
        }
        rl *= SC2; rh *= SC2;
        rl = fmaxf(rl, __shfl_xor_sync(0xffffffffu, rl, 1));
        rl = fmaxf(rl, __shfl_xor_sync(0xffffffffu, rl, 2));
        rh = fmaxf(rh, __shfl_xor_sync(0xffffffffu, rh, 1));
        rh = fmaxf(rh, __shfl_xor_sync(0xffffffffu, rh, 2));
        float mlo = fmaxf(m_lo, rl), mhi = fmaxf(m_hi, rh);
        float clo = exp2t(m_lo - mlo), chi = exp2t(m_hi - mhi);

        float suml = 0.f, sumh = 0.f;
#pragma unroll
        for (int ni = 0; ni < 8; ni++) {
            s[ni][0] = exp2t(fmaf(s[ni][0], SC2, -mlo));
            s[ni][1] = exp2t(fmaf(s[ni][1], SC2, -mlo));
            s[ni][2] = exp2t(fmaf(s[ni][2], SC2, -mhi));
            s[ni][3] = exp2t(fmaf(s[ni][3], SC2, -mhi));
            suml += s[ni][0] + s[ni][1];
            sumh += s[ni][2] + s[ni][3];
        }
        suml += __shfl_xor_sync(0xffffffffu, suml, 1);
        suml += __shfl_xor_sync(0xffffffffu, suml, 2);
        sumh += __shfl_xor_sync(0xffffffffu, sumh, 1);
        sumh += __shfl_xor_sync(0xffffffffu, sumh, 2);
        l_lo = l_lo * clo + suml;
        l_hi = l_hi * chi + sumh;
        m_lo = mlo; m_hi = mhi;

#pragma unroll
        for (int ni = 0; ni < 16; ni++) {
            o[ni][0] *= clo; o[ni][1] *= clo;
            o[ni][2] *= chi; o[ni][3] *= chi;
        }

        // O += P @ V   (P packed from registers: C-frag == A-frag pair layout)
#pragma unroll
        for (int kk = 0; kk < 4; kk++) {
            unsigned ph[4], pl[4];
            ph[0] = packbf(s[2 * kk][0], s[2 * kk][1]);
            ph[1] = packbf(s[2 * kk][2], s[2 * kk][3]);
            ph[2] = packbf(s[2 * kk + 1][0], s[2 * kk + 1][1]);
            ph[3] = packbf(s[2 * kk + 1][2], s[2 * kk + 1][3]);
            float2 u;
            u = unpackbf(ph[0]); pl[0] = packbf(s[2 * kk][0] - u.x, s[2 * kk][1] - u.y);
            u = unpackbf(ph[1]); pl[1] = packbf(s[2 * kk][2] - u.x, s[2 * kk][3] - u.y);
            u = unpackbf(ph[2]); pl[2] = packbf(s[2 * kk + 1][0] - u.x, s[2 * kk + 1][1] - u.y);
            u = unpackbf(ph[3]); pl[3] = packbf(s[2 * kk + 1][2] - u.x, s[2 * kk + 1][3] - u.y);
#pragma unroll
            for (int ni = 0; ni < 16; ni++) {
                int vb = (ni * 8 + gr) * VSW + kk * 8 + gc;
                unsigned bh[2] = {Vh[vb], Vh[vb + 4]};
                unsigned bl[2] = {Vl[vb], Vl[vb + 4]};
                mma_bf16(o[ni], ph, bh);
                mma_bf16(o[ni], ph, bl);
                mma_bf16(o[ni], pl, bh);
            }
        }
        __syncthreads();
    }

    float il = 1.f / l_lo, ih = 1.f / l_hi;
#pragma unroll
    for (int ni = 0; ni < 16; ni++) {
        int row = q0 + rb + gr;
        int col = h * HD + ni * 8 + gc * 2;
        float2 v0 = {o[ni][0] * il, o[ni][1] * il};
        float2 v1 = {o[ni][2] * ih, o[ni][3] * ih};
        *(float2*)&g_o[(size_t)row * DIM + col] = v0;
        *(float2*)&g_o[(size_t)(row + 8) * DIM + col] = v1;
    }
}

// ---------------- launch ------------------------------------------------------
static inline void cpk(const float* in, unsigned* hi, unsigned* lo, size_t nelem)
{
    int n4 = (int)(nelem / 4);
    convert_pack_k<<<(n4 + 255) / 256, 256>>>(
        (const float4*)in, (uint2*)hi, (uint2*)lo, n4);
}

extern "C" void kernel_launch(void* const* d_in, const int* in_sizes, int n_in,
                              void* d_out, int out_size)
{
    const float* x         = (const float*)d_in[0];
    const float* pe        = (const float*)d_in[1];
    const float* qkv_w     = (const float*)d_in[2];
    const float* qkv_b     = (const float*)d_in[3];
    const float* proj_w    = (const float*)d_in[4];
    const float* proj_b    = (const float*)d_in[5];
    const float* qkv_down  = (const float*)d_in[6];
    const float* qkv_up    = (const float*)d_in[7];
    const float* proj_down = (const float*)d_in[8];
    const float* proj_up   = (const float*)d_in[9];
    const float* q_scale   = (const float*)d_in[10];
    const float* k_scale   = (const float*)d_in[11];
    float* out = (float*)d_out;
    (void)in_sizes; (void)n_in; (void)out_size;

    float *gqkv, *gxa, *go, *gob;
    cudaGetSymbolAddress((void**)&gqkv, g_qkv);
    cudaGetSymbolAddress((void**)&gxa,  g_xa);
    cudaGetSymbolAddress((void**)&go,   g_o);
    cudaGetSymbolAddress((void**)&gob,  g_ob);
    unsigned *x2h, *x2l, *w1h, *w1l, *w2h, *w2l, *o2h, *o2l;
    unsigned *u1h, *u1l, *u2h, *u2l, *xa2h, *xa2l, *ob2h, *ob2l;
    cudaGetSymbolAddress((void**)&x2h, g_x2h);   cudaGetSymbolAddress((void**)&x2l, g_x2l);
    cudaGetSymbolAddress((void**)&w1h, g_w1h);   cudaGetSymbolAddress((void**)&w1l, g_w1l);
    cudaGetSymbolAddress((void**)&w2h, g_w2h);   cudaGetSymbolAddress((void**)&w2l, g_w2l);
    cudaGetSymbolAddress((void**)&o2h, g_o2h);   cudaGetSymbolAddress((void**)&o2l, g_o2l);
    cudaGetSymbolAddress((void**)&u1h, g_u1h);   cudaGetSymbolAddress((void**)&u1l, g_u1l);
    cudaGetSymbolAddress((void**)&u2h, g_u2h);   cudaGetSymbolAddress((void**)&u2l, g_u2l);
    cudaGetSymbolAddress((void**)&xa2h, g_xa2h); cudaGetSymbolAddress((void**)&xa2l, g_xa2l);
    cudaGetSymbolAddress((void**)&ob2h, g_ob2h); cudaGetSymbolAddress((void**)&ob2l, g_ob2l);

    cudaFuncSetAttribute(flash_k, cudaFuncAttributeMaxDynamicSharedMemorySize,
                         (int)FA_SMEM);

    // pre-pass packing
    cpk(x, x2h, x2l, (size_t)SEQ * DIM);
    cpk(qkv_w, w1h, w1l, (size_t)QKV_N * DIM);
    cpk(proj_w, w2h, w2l, (size_t)DIM * DIM);
    cpk(qkv_up, u1h, u1l, (size_t)QKV_N * RANK);
    cpk(proj_up, u2h, u2l, (size_t)DIM * RANK);

    // 1) xa = (x @ qkv_down^T) * scale, then pack
    lora_down_k<<<SEQ / 16, 256>>>(x, qkv_down, gxa);
    cpk(gxa, xa2h, xa2l, (size_t)SEQ * RANK);

    // 2) qkv GEMM + LoRA
    gemm_bf16s_lora_k<<<dim3(QKV_N / 128, SEQ / 128), 256>>>(
        x2h, x2l, w1h, w1l, qkv_b, xa2h, xa2l, u1h, u1l, gqkv, QKV_N, DIM);

    // 3) norm + rope + repack
    norm_rope_k<<<dim3(SEQ / 2, NH), 256>>>(pe, q_scale, k_scale);

    // 4) flash attention
    flash_k<<<dim3(SEQ / FBM, NH), 256, FA_SMEM>>>();

    // 5) proj LoRA-down + packs
    cpk(go, o2h, o2l, (size_t)SEQ * DIM);
    lora_down_k<<<SEQ / 16, 256>>>(go, proj_down, gob);
    cpk(gob, ob2h, ob2l, (size_t)SEQ * RANK);

    // 6) proj GEMM + LoRA -> out
    gemm_bf16s_lora_k<<<dim3(DIM / 128, SEQ / 128), 256>>>(
        o2h, o2l, w2h, w2l, proj_b, ob2h, ob2l, u2h, u2l, out, DIM, DIM);
}

// round 4
// speedup vs baseline: 3.7416x; 1.2232x over previous
#include <cuda_runtime.h>
#include <cuda_bf16.h>
#include <math.h>

#define SEQ 2048
#define DIM 3072
#define NH 24
#define HD 128
#define RANK 16
#define QKV_N (3 * DIM)
#define LORA_SCALE 1.0f
#define SEQW (SEQ / 2)

// ---------------- scratch (device globals; no allocations allowed) ----------
__device__ float g_qkv[(size_t)SEQ * QKV_N];
__device__ float g_xa[SEQ * RANK];
__device__ float g_ob[SEQ * RANK];
__device__ float g_o[(size_t)SEQ * DIM];

__device__ unsigned g_x2h[(size_t)SEQ * DIM / 2],   g_x2l[(size_t)SEQ * DIM / 2];
__device__ unsigned g_w1h[(size_t)QKV_N * DIM / 2], g_w1l[(size_t)QKV_N * DIM / 2];
__device__ unsigned g_w2h[(size_t)DIM * DIM / 2],   g_w2l[(size_t)DIM * DIM / 2];
__device__ unsigned g_o2h[(size_t)SEQ * DIM / 2],   g_o2l[(size_t)SEQ * DIM / 2];
__device__ unsigned g_u1h[QKV_N * RANK / 2],        g_u1l[QKV_N * RANK / 2];
__device__ unsigned g_u2h[DIM * RANK / 2],          g_u2l[DIM * RANK / 2];
__device__ unsigned g_xa2h[SEQ * RANK / 2],         g_xa2l[SEQ * RANK / 2];
__device__ unsigned g_ob2h[SEQ * RANK / 2],         g_ob2l[SEQ * RANK / 2];
__device__ unsigned g_q2h[(size_t)NH * SEQ * HD / 2], g_q2l[(size_t)NH * SEQ * HD / 2];
__device__ unsigned g_k2h[(size_t)NH * SEQ * HD / 2], g_k2l[(size_t)NH * SEQ * HD / 2];
__device__ unsigned g_v2h[(size_t)NH * HD * SEQW],    g_v2l[(size_t)NH * HD * SEQW];

// ---------------- helpers ----------------------------------------------------
__device__ __forceinline__ void mma_bf16(float* d, const unsigned* a, const unsigned* b)
{
    asm volatile(
        "mma.sync.aligned.m16n8k16.row.col.f32.bf16.bf16.f32 "
        "{%0,%1,%2,%3},{%4,%5,%6,%7},{%8,%9},{%0,%1,%2,%3};\n"
        : "+f"(d[0]), "+f"(d[1]), "+f"(d[2]), "+f"(d[3])
        : "r"(a[0]), "r"(a[1]), "r"(a[2]), "r"(a[3]), "r"(b[0]), "r"(b[1]));
}

__device__ __forceinline__ void ldsm4(unsigned* r, unsigned addr)
{
    asm volatile("ldmatrix.sync.aligned.m8n8.x4.shared.b16 {%0,%1,%2,%3}, [%4];"
                 : "=r"(r[0]), "=r"(r[1]), "=r"(r[2]), "=r"(r[3]) : "r"(addr));
}

__device__ __forceinline__ void cpa16(unsigned dst, const void* src)
{
    asm volatile("cp.async.cg.shared.global [%0], [%1], 16;" :: "r"(dst), "l"(src));
}
#define CP_COMMIT() asm volatile("cp.async.commit_group;")
#define CP_WAIT1()  asm volatile("cp.async.wait_group 1;")
#define CP_WAIT0()  asm volatile("cp.async.wait_group 0;")

__device__ __forceinline__ unsigned packbf(float v0, float v1)
{
    unsigned r;
    asm("cvt.rn.bf16x2.f32 %0, %1, %2;" : "=r"(r) : "f"(v1), "f"(v0));
    return r;
}
__device__ __forceinline__ float2 unpackbf(unsigned w)
{
    float2 f;
    f.x = __uint_as_float(w << 16);
    f.y = __uint_as_float(w & 0xffff0000u);
    return f;
}

__device__ __forceinline__ float exp2t(float x)
{
    x = fmaxf(x, -120.f);
    float r = rintf(x);
    float t = (x - r) * 0.6931471805599453f;
    float p = fmaf(t, 0.0083333333f, 0.041666666f);
    p = fmaf(t, p, 0.16666667f);
    p = fmaf(t, p, 0.5f);
    p = fmaf(t, p, 1.0f);
    p = fmaf(t, p, 1.0f);
    return __int_as_float(__float_as_int(p) + (((int)r) << 23));
}

// ---------------- fp32 -> (hi, lo) bf16-pair pack -----------------------------
__global__ void __launch_bounds__(256) convert_pack_k(
    const float4* __restrict__ in, uint2* __restrict__ hi, uint2* __restrict__ lo, int n4)
{
    int i = blockIdx.x * 256 + threadIdx.x;
    if (i >= n4) return;
    float4 v = in[i];
    unsigned h0 = packbf(v.x, v.y), h1 = packbf(v.z, v.w);
    float2 a = unpackbf(h0), b = unpackbf(h1);
    unsigned l0 = packbf(v.x - a.x, v.y - a.y);
    unsigned l1 = packbf(v.z - b.x, v.w - b.y);
    hi[i] = make_uint2(h0, h1);
    lo[i] = make_uint2(l0, l1);
}

// ---------------- LoRA down-projection ----------------------------------------
__global__ void __launch_bounds__(256) lora_down_k(
    const float* __restrict__ A, const float* __restrict__ D, float* __restrict__ out)
{
    int m = blockIdx.x * 16 + (threadIdx.x >> 4);
    int r = threadIdx.x & 15;
    const float4* a4 = (const float4*)(A + (size_t)m * DIM);
    const float4* d4 = (const float4*)(D + (size_t)r * DIM);
    float acc = 0.f;
#pragma unroll 4
    for (int k = 0; k < DIM / 4; k++) {
        float4 va = a4[k], vd = d4[k];
        acc = fmaf(va.x, vd.x, acc);
        acc = fmaf(va.y, vd.y, acc);
        acc = fmaf(va.z, vd.z, acc);
        acc = fmaf(va.w, vd.w, acc);
    }
    out[m * RANK + r] = acc * LORA_SCALE;
}

// ---------------- split-bf16 GEMM: cp.async pipeline + ldmatrix ---------------
#define GAH 0
#define GAL 2560
#define GBH 5120
#define GBL 7680
#define GST 10240                       // words per stage
#define GEMM_SMEM (2 * GST * 4)

__global__ void __launch_bounds__(256, 2) gemm_bf16s_lora_k(
    const unsigned* __restrict__ Ahg, const unsigned* __restrict__ Alg,
    const unsigned* __restrict__ Whg, const unsigned* __restrict__ Wlg,
    const float* __restrict__ bias,
    const unsigned* __restrict__ LAh, const unsigned* __restrict__ LAl,
    const unsigned* __restrict__ LUh, const unsigned* __restrict__ LUl,
    float* __restrict__ C, int N, int K)
{
    extern __shared__ unsigned smg[];
    const unsigned sb = (unsigned)__cvta_generic_to_shared(smg);
    const int Kw = K / 2;

    const int tid = threadIdx.x;
    const int lane = tid & 31, wid = tid >> 5;
    const int wm = (wid & 1) * 64, wn = (wid >> 1) * 32;
    const int gr = lane >> 2, gc = lane & 3;
    const int bm = blockIdx.y * 128, bn = blockIdx.x * 128;

    const int aro = lane & 15, aco = (lane >> 4) << 2;
    const int bro = ((lane >> 4) << 3) + (lane & 7), bco = ((lane >> 3) & 1) << 2;

    float acc[4][4][4];
#pragma unroll
    for (int i = 0; i < 4; i++)
#pragma unroll
        for (int j = 0; j < 4; j++)
#pragma unroll
            for (int q = 0; q < 4; q++) acc[i][j][q] = 0.f;

    const int lrow = tid >> 2, lwq = (tid & 3) * 4;

#define G_ISSUE(K0, ST) do {                                               \
        unsigned base_ = sb + (ST) * (GST * 4);                            \
        _Pragma("unroll")                                                  \
        for (int i_ = 0; i_ < 2; i_++) {                                   \
            int r_ = lrow + i_ * 64;                                       \
            size_t ai_ = (size_t)(bm + r_) * Kw + (K0) + lwq;              \
            size_t bi_ = (size_t)(bn + r_) * Kw + (K0) + lwq;              \
            cpa16(base_ + (GAH + r_ * 20 + lwq) * 4, Ahg + ai_);           \
            cpa16(base_ + (GAL + r_ * 20 + lwq) * 4, Alg + ai_);           \
            cpa16(base_ + (GBH + r_ * 20 + lwq) * 4, Whg + bi_);           \
            cpa16(base_ + (GBL + r_ * 20 + lwq) * 4, Wlg + bi_);           \
        }                                                                  \
    } while (0)

    const int nk = Kw / 16;
    G_ISSUE(0, 0);
    CP_COMMIT();

    for (int it = 0; it < nk; it++) {
        if (it + 1 < nk) {
            G_ISSUE((it + 1) * 16, (it + 1) & 1);
            CP_COMMIT();
            CP_WAIT1();
        } else {
            CP_WAIT0();
        }
        __syncthreads();
        unsigned base = sb + (it & 1) * (GST * 4);
#pragma unroll
        for (int kk = 0; kk < 2; kk++) {
            unsigned bh[2][4], bl[2][4];
#pragma unroll
            for (int nj = 0; nj < 2; nj++) {
                unsigned ba = base + (GBH + (wn + nj * 16 + bro) * 20 + kk * 8 + bco) * 4;
                ldsm4(bh[nj], ba);
                ldsm4(bl[nj], ba + (GBL - GBH) * 4);
            }
#pragma unroll
            for (int mi = 0; mi < 4; mi++) {
                unsigned aa = base + (GAH + (wm + mi * 16 + aro) * 20 + kk * 8 + aco) * 4;
                unsigned ah[4], al[4];
                ldsm4(ah, aa);
                ldsm4(al, aa + (GAL - GAH) * 4);
#pragma unroll
                for (int ni = 0; ni < 4; ni++) {
                    const unsigned* pbh = &bh[ni >> 1][(ni & 1) * 2];
                    const unsigned* pbl = &bl[ni >> 1][(ni & 1) * 2];
                    mma_bf16(acc[mi][ni], ah, pbh);
                    mma_bf16(acc[mi][ni], ah, pbl);
                    mma_bf16(acc[mi][ni], al, pbh);
                }
            }
        }
        __syncthreads();
    }

    // LoRA extra K-step (rank 16 = 8 words) using stage-0 buffers
    {
        int row = tid >> 1, wq = (tid & 1) * 4;
        *(uint4*)&smg[GAH + row * 20 + wq] = *(const uint4*)&LAh[(size_t)(bm + row) * 8 + wq];
        *(uint4*)&smg[GAL + row * 20 + wq] = *(const uint4*)&LAl[(size_t)(bm + row) * 8 + wq];
        *(uint4*)&smg[GBH + row * 20 + wq] = *(const uint4*)&LUh[(size_t)(bn + row) * 8 + wq];
        *(uint4*)&smg[GBL + row * 20 + wq] = *(const uint4*)&LUl[(size_t)(bn + row) * 8 + wq];
        __syncthreads();
        unsigned bh[2][4], bl[2][4];
#pragma unroll
        for (int nj = 0; nj < 2; nj++) {
            unsigned ba = sb + (GBH + (wn + nj * 16 + bro) * 20 + bco) * 4;
            ldsm4(bh[nj], ba);
            ldsm4(bl[nj], ba + (GBL - GBH) * 4);
        }
#pragma unroll
        for (int mi = 0; mi < 4; mi++) {
            unsigned aa = sb + (GAH + (wm + mi * 16 + aro) * 20 + aco) * 4;
            unsigned ah[4], al[4];
            ldsm4(ah, aa);
            ldsm4(al, aa + (GAL - GAH) * 4);
#pragma unroll
            for (int ni = 0; ni < 4; ni++) {
                const unsigned* pbh = &bh[ni >> 1][(ni & 1) * 2];
                const unsigned* pbl = &bl[ni >> 1][(ni & 1) * 2];
                mma_bf16(acc[mi][ni], ah, pbh);
                mma_bf16(acc[mi][ni], ah, pbl);
                mma_bf16(acc[mi][ni], al, pbh);
            }
        }
    }

#pragma unroll
    for (int mi = 0; mi < 4; mi++) {
        int row = bm + wm + mi * 16 + gr;
#pragma unroll
        for (int ni = 0; ni < 4; ni++) {
            int col = bn + wn + ni * 8 + gc * 2;
            float b0 = __ldg(&bias[col]), b1 = __ldg(&bias[col + 1]);
            float2 v0 = {acc[mi][ni][0] + b0, acc[mi][ni][1] + b1};
            float2 v1 = {acc[mi][ni][2] + b0, acc[mi][ni][3] + b1};
            *(float2*)&C[(size_t)row * N + col] = v0;
            *(float2*)&C[(size_t)(row + 8) * N + col] = v1;
        }
    }
}

// ---------------- QK RMSNorm + RoPE + packed repack ---------------------------
__global__ void __launch_bounds__(256) norm_rope_k(
    const float* __restrict__ pe,
    const float* __restrict__ q_scale, const float* __restrict__ k_scale)
{
    const int half = threadIdx.x >> 7;
    const int t = threadIdx.x & 127;
    const int l = blockIdx.x * 2 + half;
    const int h = blockIdx.y;

    const float* row = g_qkv + (size_t)l * QKV_N + h * HD;
    float qv = row[t], kv = row[DIM + t], vv = row[2 * DIM + t];

    __shared__ float red[2][8];
    __shared__ float qr[2][HD], kr[2][HD], qo_[2][HD], ko_[2][HD], vr[2][HD];

    float s1 = qv * qv, s2 = kv * kv;
#pragma unroll
    for (int o = 16; o > 0; o >>= 1) {
        s1 += __shfl_xor_sync(0xffffffffu, s1, o);
        s2 += __shfl_xor_sync(0xffffffffu, s2, o);
    }
    int w = (t >> 5);
    if ((t & 31) == 0) { red[half][w] = s1; red[half][4 + w] = s2; }
    __syncthreads();
    float msq = (red[half][0] + red[half][1] + red[half][2] + red[half][3]) * (1.f / HD);
    float msk = (red[half][4] + red[half][5] + red[half][6] + red[half][7]) * (1.f / HD);
    qr[half][t] = qv * rsqrtf(msq + 1e-6f) * q_scale[t];
    kr[half][t] = kv * rsqrtf(msk + 1e-6f) * k_scale[t];
    vr[half][t] = vv;
    __syncthreads();

    int i = t >> 1;
    const float* p = pe + ((size_t)l * (HD / 2) + i) * 4;
    float c = p[0], s = p[2];
    float q0 = qr[half][2 * i], q1 = qr[half][2 * i + 1];
    float k0 = kr[half][2 * i], k1 = kr[half][2 * i + 1];
    qo_[half][t] = (t & 1) ? fmaf(s, q0, c * q1) : fmaf(c, q0, -s * q1);
    ko_[half][t] = (t & 1) ? fmaf(s, k0, c * k1) : fmaf(c, k0, -s * k1);
    __syncthreads();

    if (t < 64) {
        size_t base = ((size_t)h * SEQ + l) * (HD / 2) + t;
        float a0 = qo_[half][2 * t], a1 = qo_[half][2 * t + 1];
        unsigned hq = packbf(a0, a1);
        float2 u = unpackbf(hq);
        g_q2h[base] = hq;
        g_q2l[base] = packbf(a0 - u.x, a1 - u.y);
        float b0 = ko_[half][2 * t], b1 = ko_[half][2 * t + 1];
        unsigned hk = packbf(b0, b1);
        u = unpackbf(hk);
        g_k2h[base] = hk;
        g_k2l[base] = packbf(b0 - u.x, b1 - u.y);
    }
    if (half == 0) {
        float v0 = vr[0][t], v1 = vr[1][t];
        unsigned hv = packbf(v0, v1);
        float2 u = unpackbf(hv);
        size_t base = ((size_t)h * HD + t) * SEQW + blockIdx.x;
        g_v2h[base] = hv;
        g_v2l[base] = packbf(v0 - u.x, v1 - u.y);
    }
}

// ---------------- flash attention: cp.async pipeline + ldmatrix ---------------
#define FBM 128
#define FBN 64
#define QSW 68
#define VSW 36
#define FQH 0
#define FQL 8704
#define FST0 17408
#define FKH 0
#define FKL 4352
#define FVH 8704
#define FVL 13312
#define FSTW 17920
#define FA_SMEM ((FST0 + 2 * FSTW) * 4)

__global__ void __launch_bounds__(256) flash_k()
{
    extern __shared__ unsigned smf[];
    const unsigned sb = (unsigned)__cvta_generic_to_shared(smf);

    const int h = blockIdx.y;
    const int q0 = blockIdx.x * FBM;
    const int tid = threadIdx.x;
    const int lane = tid & 31, wid = tid >> 5;
    const int gr = lane >> 2, gc = lane & 3;
    const int rb = wid * 16;

    const int aro = lane & 15, aco = (lane >> 4) << 2;
    const int bro = ((lane >> 4) << 3) + (lane & 7), bco = ((lane >> 3) & 1) << 2;

    // Q tile (plain loads)
#pragma unroll
    for (int i = 0; i < 8; i++) {
        int idx = tid + i * 256;
        int r = idx >> 4, wq = (idx & 15) * 4;
        size_t src = ((size_t)h * SEQ + q0 + r) * 64 + wq;
        *(uint4*)&smf[FQH + r * QSW + wq] = *(const uint4*)&g_q2h[src];
        *(uint4*)&smf[FQL + r * QSW + wq] = *(const uint4*)&g_q2l[src];
    }

#define F_ISSUE(KT, ST) do {                                                \
        unsigned base_ = sb + (FST0 + (ST) * FSTW) * 4;                     \
        _Pragma("unroll")                                                   \
        for (int i_ = 0; i_ < 4; i_++) {                                    \
            int idx_ = tid + i_ * 256;                                      \
            int r_ = idx_ >> 4, wq_ = (idx_ & 15) * 4;                      \
            size_t ks_ = ((size_t)h * SEQ + (KT) + r_) * 64 + wq_;          \
            cpa16(base_ + (FKH + r_ * QSW + wq_) * 4, g_k2h + ks_);         \
            cpa16(base_ + (FKL + r_ * QSW + wq_) * 4, g_k2l + ks_);         \
            int rv_ = idx_ >> 3, wv_ = (idx_ & 7) * 4;                      \
            size_t vs_ = ((size_t)h * HD + rv_) * SEQW + (KT) / 2 + wv_;    \
            cpa16(base_ + (FVH + rv_ * VSW + wv_) * 4, g_v2h + vs_);        \
            cpa16(base_ + (FVL + rv_ * VSW + wv_) * 4, g_v2l + vs_);        \
        }                                                                   \
    } while (0)

    float o[16][4];
#pragma unroll
    for (int i = 0; i < 16; i++)
#pragma unroll
        for (int j = 0; j < 4; j++) o[i][j] = 0.f;
    float m_lo = -1e30f, m_hi = -1e30f, l_lo = 0.f, l_hi = 0.f;
    const float SC2 = 0.088388347648318447f * 1.4426950408889634f;

    F_ISSUE(0, 0);
    CP_COMMIT();

    const int nkt = SEQ / FBN;
    for (int it = 0; it < nkt; it++) {
        if (it + 1 < nkt) {
            F_ISSUE((it + 1) * FBN, (it + 1) & 1);
            CP_COMMIT();
            CP_WAIT1();
        } else {
            CP_WAIT0();
        }
        __syncthreads();
        unsigned kbase = sb + (FST0 + (it & 1) * FSTW) * 4;

        // S = Q K^T
        float s[8][4];
#pragma unroll
        for (int i = 0; i < 8; i++)
#pragma unroll
            for (int j = 0; j < 4; j++) s[i][j] = 0.f;
#pragma unroll
        for (int kk = 0; kk < 8; kk++) {
            unsigned qa = sb + (FQH + (rb + aro) * QSW + kk * 8 + aco) * 4;
            unsigned qh[4], ql[4];
            ldsm4(qh, qa);
            ldsm4(ql, qa + (FQL - FQH) * 4);
#pragma unroll
            for (int nj = 0; nj < 4; nj++) {
                unsigned ka = kbase + (FKH + (nj * 16 + bro) * QSW + kk * 8 + bco) * 4;
                unsigned kh[4], kl[4];
                ldsm4(kh, ka);
                ldsm4(kl, ka + (FKL - FKH) * 4);
                mma_bf16(s[2 * nj],     qh, kh);
                mma_bf16(s[2 * nj],     qh, kl);
                mma_bf16(s[2 * nj],     ql, kh);
                mma_bf16(s[2 * nj + 1], qh, kh + 2);
                mma_bf16(s[2 * nj + 1], qh, kl + 2);
                mma_bf16(s[2 * nj + 1], ql, kh + 2);
            }
        }

        // online softmax
        float rl = -1e30f, rh = -1e30f;
#pragma unroll
        for (int ni = 0; ni < 8; ni++) {
            rl = fmaxf(rl, fmaxf(s[ni][0], s[ni][1]));
            rh = fmaxf(rh, fmaxf(s[ni][2], s[ni][3]));
        }
        rl *= SC2; rh *= SC2;
        rl = fmaxf(rl, __shfl_xor_sync(0xffffffffu, rl, 1));
        rl = fmaxf(rl, __shfl_xor_sync(0xffffffffu, rl, 2));
        rh = fmaxf(rh, __shfl_xor_sync(0xffffffffu, rh, 1));
        rh = fmaxf(rh, __shfl_xor_sync(0xffffffffu, rh, 2));
        float mlo = fmaxf(m_lo, rl), mhi = fmaxf(m_hi, rh);
        float clo = exp2t(m_lo - mlo), chi = exp2t(m_hi - mhi);

        float suml = 0.f, sumh = 0.f;
#pragma unroll
        for (int ni = 0; ni < 8; ni++) {
            s[ni][0] = exp2t(fmaf(s[ni][0], SC2, -mlo));
            s[ni][1] = exp2t(fmaf(s[ni][1], SC2, -mlo));
            s[ni][2] = exp2t(fmaf(s[ni][2], SC2, -mhi));
            s[ni][3] = exp2t(fmaf(s[ni][3], SC2, -mhi));
            suml += s[ni][0] + s[ni][1];
            sumh += s[ni][2] + s[ni][3];
        }
        suml += __shfl_xor_sync(0xffffffffu, suml, 1);
        suml += __shfl_xor_sync(0xffffffffu, suml, 2);
        sumh += __shfl_xor_sync(0xffffffffu, sumh, 1);
        sumh += __shfl_xor_sync(0xffffffffu, sumh, 2);
        l_lo = l_lo * clo + suml;
        l_hi = l_hi * chi + sumh;
        m_lo = mlo; m_hi = mhi;

#pragma unroll
        for (int ni = 0; ni < 16; ni++) {
            o[ni][0] *= clo; o[ni][1] *= clo;
            o[ni][2] *= chi; o[ni][3] *= chi;
        }

        // O += P @ V
#pragma unroll
        for (int kk = 0; kk < 4; kk++) {
            unsigned ph[4], pl[4];
            ph[0] = packbf(s[2 * kk][0], s[2 * kk][1]);
            ph[1] = packbf(s[2 * kk][2], s[2 * kk][3]);
            ph[2] = packbf(s[2 * kk + 1][0], s[2 * kk + 1][1]);
            ph[3] = packbf(s[2 * kk + 1][2], s[2 * kk + 1][3]);
            float2 u;
            u = unpackbf(ph[0]); pl[0] = packbf(s[2 * kk][0] - u.x, s[2 * kk][1] - u.y);
            u = unpackbf(ph[1]); pl[1] = packbf(s[2 * kk][2] - u.x, s[2 * kk][3] - u.y);
            u = unpackbf(ph[2]); pl[2] = packbf(s[2 * kk + 1][0] - u.x, s[2 * kk + 1][1] - u.y);
            u = unpackbf(ph[3]); pl[3] = packbf(s[2 * kk + 1][2] - u.x, s[2 * kk + 1][3] - u.y);
#pragma unroll
            for (int nj = 0; nj < 8; nj++) {
                unsigned va = kbase + (FVH + (nj * 16 + bro) * VSW + kk * 8 + bco) * 4;
                unsigned vh[4], vl[4];
                ldsm4(vh, va);
                ldsm4(vl, va + (FVL - FVH) * 4);
                mma_bf16(o[2 * nj],     ph, vh);
                mma_bf16(o[2 * nj],     ph, vl);
                mma_bf16(o[2 * nj],     pl, vh);
                mma_bf16(o[2 * nj + 1], ph, vh + 2);
                mma_bf16(o[2 * nj + 1], ph, vl + 2);
                mma_bf16(o[2 * nj + 1], pl, vh + 2);
            }
        }
        __syncthreads();
    }

    float il = 1.f / l_lo, ih = 1.f / l_hi;
#pragma unroll
    for (int ni = 0; ni < 16; ni++) {
        int row = q0 + rb + gr;
        int col = h * HD + ni * 8 + gc * 2;
        float2 v0 = {o[ni][0] * il, o[ni][1] * il};
        float2 v1 = {o[ni][2] * ih, o[ni][3] * ih};
        *(float2*)&g_o[(size_t)row * DIM + col] = v0;
        *(float2*)&g_o[(size_t)(row + 8) * DIM + col] = v1;
    }
}

// ---------------- launch ------------------------------------------------------
static inline void cpk(const float* in, unsigned* hi, unsigned* lo, size_t nelem)
{
    int n4 = (int)(nelem / 4);
    convert_pack_k<<<(n4 + 255) / 256, 256>>>(
        (const float4*)in, (uint2*)hi, (uint2*)lo, n4);
}

extern "C" void kernel_launch(void* const* d_in, const int* in_sizes, int n_in,
                              void* d_out, int out_size)
{
    const float* x         = (const float*)d_in[0];
    const float* pe        = (const float*)d_in[1];
    const float* qkv_w     = (const float*)d_in[2];
    const float* qkv_b     = (const float*)d_in[3];
    const float* proj_w    = (const float*)d_in[4];
    const float* proj_b    = (const float*)d_in[5];
    const float* qkv_down  = (const float*)d_in[6];
    const float* qkv_up    = (const float*)d_in[7];
    const float* proj_down = (const float*)d_in[8];
    const float* proj_up   = (const float*)d_in[9];
    const float* q_scale   = (const float*)d_in[10];
    const float* k_scale   = (const float*)d_in[11];
    float* out = (float*)d_out;
    (void)in_sizes; (void)n_in; (void)out_size;

    float *gqkv, *gxa, *go, *gob;
    cudaGetSymbolAddress((void**)&gqkv, g_qkv);
    cudaGetSymbolAddress((void**)&gxa,  g_xa);
    cudaGetSymbolAddress((void**)&go,   g_o);
    cudaGetSymbolAddress((void**)&gob,  g_ob);
    unsigned *x2h, *x2l, *w1h, *w1l, *w2h, *w2l, *o2h, *o2l;
    unsigned *u1h, *u1l, *u2h, *u2l, *xa2h, *xa2l, *ob2h, *ob2l;
    cudaGetSymbolAddress((void**)&x2h, g_x2h);   cudaGetSymbolAddress((void**)&x2l, g_x2l);
    cudaGetSymbolAddress((void**)&w1h, g_w1h);   cudaGetSymbolAddress((void**)&w1l, g_w1l);
    cudaGetSymbolAddress((void**)&w2h, g_w2h);   cudaGetSymbolAddress((void**)&w2l, g_w2l);
    cudaGetSymbolAddress((void**)&o2h, g_o2h);   cudaGetSymbolAddress((void**)&o2l, g_o2l);
    cudaGetSymbolAddress((void**)&u1h, g_u1h);   cudaGetSymbolAddress((void**)&u1l, g_u1l);
    cudaGetSymbolAddress((void**)&u2h, g_u2h);   cudaGetSymbolAddress((void**)&u2l, g_u2l);
    cudaGetSymbolAddress((void**)&xa2h, g_xa2h); cudaGetSymbolAddress((void**)&xa2l, g_xa2l);
    cudaGetSymbolAddress((void**)&ob2h, g_ob2h); cudaGetSymbolAddress((void**)&ob2l, g_ob2l);

    cudaFuncSetAttribute(flash_k, cudaFuncAttributeMaxDynamicSharedMemorySize,
                         (int)FA_SMEM);
    cudaFuncSetAttribute(gemm_bf16s_lora_k, cudaFuncAttributeMaxDynamicSharedMemorySize,
                         (int)GEMM_SMEM);

    // pre-pass packing
    cpk(x, x2h, x2l, (size_t)SEQ * DIM);
    cpk(qkv_w, w1h, w1l, (size_t)QKV_N * DIM);
    cpk(proj_w, w2h, w2l, (size_t)DIM * DIM);
    cpk(qkv_up, u1h, u1l, (size_t)QKV_N * RANK);
    cpk(proj_up, u2h, u2l, (size_t)DIM * RANK);

    // 1) xa = (x @ qkv_down^T) * scale, pack
    lora_down_k<<<SEQ / 16, 256>>>(x, qkv_down, gxa);
    cpk(gxa, xa2h, xa2l, (size_t)SEQ * RANK);

    // 2) qkv GEMM + LoRA
    gemm_bf16s_lora_k<<<dim3(QKV_N / 128, SEQ / 128), 256, GEMM_SMEM>>>(
        x2h, x2l, w1h, w1l, qkv_b, xa2h, xa2l, u1h, u1l, gqkv, QKV_N, DIM);

    // 3) norm + rope + repack
    norm_rope_k<<<dim3(SEQ / 2, NH), 256>>>(pe, q_scale, k_scale);

    // 4) flash attention
    flash_k<<<dim3(SEQ / FBM, NH), 256, FA_SMEM>>>();

    // 5) proj LoRA-down + packs
    cpk(go, o2h, o2l, (size_t)SEQ * DIM);
    lora_down_k<<<SEQ / 16, 256>>>(go, proj_down, gob);
    cpk(gob, ob2h, ob2l, (size_t)SEQ * RANK);

    // 6) proj GEMM + LoRA -> out
    gemm_bf16s_lora_k<<<dim3(DIM / 128, SEQ / 128), 256, GEMM_SMEM>>>(
        o2h, o2l, w2h, w2l, proj_b, ob2h, ob2l, u2h, u2l, out, DIM, DIM);
}